// round 1
// baseline (speedup 1.0000x reference)
#include <cuda_runtime.h>
#include <math.h>

// Problem constants (fixed by the dataset)
#define NTOT 32768
#define NB   8
#define DIN  64
#define MC   8192
#define KN   32
#define PPC  4096           // points per cloud = NTOT/NB
#define R2   0.04f          // radius^2

// ---------------- scratch (static device arrays; no allocation) -------------
__device__ int g_nbr[MC * KN];
__device__ int g_val[MC * KN];

// ---------------- packed fp32x2 FMA (sm_100+ PTX) ---------------------------
__device__ __forceinline__ float2 ffma2(float2 a, float2 b, float2 c) {
    float2 d;
    asm("fma.rn.f32x2 %0, %1, %2, %3;"
        : "=l"(reinterpret_cast<unsigned long long&>(d))
        : "l"(reinterpret_cast<unsigned long long&>(a)),
          "l"(reinterpret_cast<unsigned long long&>(b)),
          "l"(reinterpret_cast<unsigned long long&>(c)));
    return d;
}

// ============================================================================
// Kernel 1: exact KNN (k=32) per center within its own cloud + ball mask.
// One block per center, 256 threads. Distances for all 4096 candidates go to
// shared; 32 sequential argmin rounds with lower-index tie-break (matches
// jax.lax.top_k tie semantics for set selection).
// ============================================================================
__global__ __launch_bounds__(256) void knn_kernel(
    const float* __restrict__ pos,
    const int*   __restrict__ batch,
    const int*   __restrict__ idx)
{
    __shared__ float sd[PPC];
    __shared__ float swv[8];
    __shared__ int   swi[8];
    __shared__ float sc[4];
    __shared__ int   sbase;

    const int m   = blockIdx.x;
    const int tid = threadIdx.x;

    if (tid == 0) {
        int ci = idx[m];
        float cx = pos[3 * ci], cy = pos[3 * ci + 1], cz = pos[3 * ci + 2];
        sc[0] = cx; sc[1] = cy; sc[2] = cz;
        sc[3] = cx * cx + cy * cy + cz * cz;
        sbase = batch[ci] * PPC;
    }
    __syncthreads();

    const float cx = sc[0], cy = sc[1], cz = sc[2], cc = sc[3];
    const int base = sbase;

    // distances (same expansion form as the reference: |c|^2+|p|^2-2 c.p)
    #pragma unroll
    for (int r = 0; r < PPC / 256; r++) {
        int j = tid + r * 256;
        const float* p = pos + 3 * (base + j);
        float px = p[0], py = p[1], pz = p[2];
        float pp  = px * px + py * py + pz * pz;
        float dot = cx * px + cy * py + cz * pz;
        sd[j] = (cc + pp) - 2.0f * dot;
    }
    __syncthreads();

    const int lane = tid & 31, w = tid >> 5;

    for (int k = 0; k < KN; k++) {
        float mv = 3.4e38f;
        int   mi = 0x7fffffff;
        #pragma unroll
        for (int r = 0; r < PPC / 256; r++) {
            int j = tid + r * 256;
            float v = sd[j];
            if (v < mv) { mv = v; mi = j; }      // ascending j keeps lowest index on tie
        }
        #pragma unroll
        for (int off = 16; off; off >>= 1) {
            float ov = __shfl_down_sync(0xffffffffu, mv, off);
            int   oi = __shfl_down_sync(0xffffffffu, mi, off);
            if (ov < mv || (ov == mv && oi < mi)) { mv = ov; mi = oi; }
        }
        if (lane == 0) { swv[w] = mv; swi[w] = mi; }
        __syncthreads();
        if (tid == 0) {
            float bv = swv[0]; int bi = swi[0];
            #pragma unroll
            for (int t = 1; t < 8; t++) {
                if (swv[t] < bv || (swv[t] == bv && swi[t] < bi)) { bv = swv[t]; bi = swi[t]; }
            }
            g_nbr[m * KN + k] = base + bi;
            g_val[m * KN + k] = (bv <= R2) ? 1 : 0;
            sd[bi] = 3.4e38f;
        }
        __syncthreads();
    }
}

// ============================================================================
// Kernel 2: edge MLP + masked max aggregation. One block per center, 128 thr.
// Activations live transposed in shared: act[i][edge], second dim padded to 34
// so that float2 row-pair loads broadcast and transposed stores are only
// 4-way conflicted. Each thread owns an 8-row x 4-col tile as f32x2 pairs.
// Weights are streamed from global (L1/L2 resident: 226 KB total, shared by
// all 8192 blocks).
// ============================================================================
#define APAD 34

template <int DINL, int COLS>
__device__ __forceinline__ void layer_fc(
    const float* __restrict__ Ash, const float* __restrict__ W,
    const float* __restrict__ bias, float* __restrict__ Bout,
    int c0, int r0)
{
    float2 acc[4][4];
    #pragma unroll
    for (int ccx = 0; ccx < 4; ccx++) {
        float b = __ldg(bias + c0 + ccx);
        #pragma unroll
        for (int q = 0; q < 4; q++) acc[q][ccx] = make_float2(b, b);
    }
    #pragma unroll 4
    for (int i = 0; i < DINL; i++) {
        float4 wv = __ldg((const float4*)(W + i * COLS + c0));
        float2 wp[4] = { make_float2(wv.x, wv.x), make_float2(wv.y, wv.y),
                         make_float2(wv.z, wv.z), make_float2(wv.w, wv.w) };
        const float2* arow = (const float2*)(Ash + i * APAD + r0);
        float2 a0 = arow[0], a1 = arow[1], a2 = arow[2], a3 = arow[3];
        #pragma unroll
        for (int ccx = 0; ccx < 4; ccx++) {
            acc[0][ccx] = ffma2(a0, wp[ccx], acc[0][ccx]);
            acc[1][ccx] = ffma2(a1, wp[ccx], acc[1][ccx]);
            acc[2][ccx] = ffma2(a2, wp[ccx], acc[2][ccx]);
            acc[3][ccx] = ffma2(a3, wp[ccx], acc[3][ccx]);
        }
    }
    #pragma unroll
    for (int ccx = 0; ccx < 4; ccx++)
        #pragma unroll
        for (int q = 0; q < 4; q++) {
            float2 v = acc[q][ccx];
            v.x = fmaxf(v.x, 0.0f);
            v.y = fmaxf(v.y, 0.0f);
            *(float2*)(Bout + (c0 + ccx) * APAD + r0 + 2 * q) = v;
        }
}

template <int DINL, int COLS>
__device__ __forceinline__ void layer_fc_max(
    const float* __restrict__ Ash, const float* __restrict__ W,
    const float* __restrict__ bias, const int* __restrict__ sval,
    float* __restrict__ part, int c0, int r0, int rg, int g)
{
    float2 acc[4][4];
    #pragma unroll
    for (int ccx = 0; ccx < 4; ccx++) {
        float b = __ldg(bias + c0 + ccx);
        #pragma unroll
        for (int q = 0; q < 4; q++) acc[q][ccx] = make_float2(b, b);
    }
    #pragma unroll 4
    for (int i = 0; i < DINL; i++) {
        float4 wv = __ldg((const float4*)(W + i * COLS + c0));
        float2 wp[4] = { make_float2(wv.x, wv.x), make_float2(wv.y, wv.y),
                         make_float2(wv.z, wv.z), make_float2(wv.w, wv.w) };
        const float2* arow = (const float2*)(Ash + i * APAD + r0);
        float2 a0 = arow[0], a1 = arow[1], a2 = arow[2], a3 = arow[3];
        #pragma unroll
        for (int ccx = 0; ccx < 4; ccx++) {
            acc[0][ccx] = ffma2(a0, wp[ccx], acc[0][ccx]);
            acc[1][ccx] = ffma2(a1, wp[ccx], acc[1][ccx]);
            acc[2][ccx] = ffma2(a2, wp[ccx], acc[2][ccx]);
            acc[3][ccx] = ffma2(a3, wp[ccx], acc[3][ccx]);
        }
    }
    const float NEGINF = __int_as_float(0xff800000);
    #pragma unroll
    for (int ccx = 0; ccx < 4; ccx++) {
        float mm = NEGINF;
        #pragma unroll
        for (int q = 0; q < 4; q++) {
            float2 v = acc[q][ccx];
            float hx = fmaxf(v.x, 0.0f);
            float hy = fmaxf(v.y, 0.0f);
            if (sval[r0 + 2 * q])     mm = fmaxf(mm, hx);
            if (sval[r0 + 2 * q + 1]) mm = fmaxf(mm, hy);
        }
        part[rg * 128 + g * 4 + ccx] = mm;
    }
}

__global__ __launch_bounds__(128) void mlp_kernel(
    const float* __restrict__ x,   const float* __restrict__ pos,
    const int*   __restrict__ batch, const int* __restrict__ idx,
    const float* __restrict__ W1, const float* __restrict__ b1,
    const float* __restrict__ W2, const float* __restrict__ b2,
    const float* __restrict__ W3, const float* __restrict__ b3,
    float* __restrict__ out)
{
    __shared__ __align__(16) float A[128 * APAD];
    __shared__ __align__(16) float Bsh[128 * APAD];
    __shared__ float part[512];
    __shared__ int   snbr[KN];
    __shared__ int   sval[KN];
    __shared__ float sctr[3];

    const int m   = blockIdx.x;
    const int tid = threadIdx.x;
    const int g   = tid & 31;        // column group
    const int rg  = tid >> 5;        // row group
    const int c0  = g * 4;
    const int r0  = rg * 8;

    if (tid < KN) {
        snbr[tid] = g_nbr[m * KN + tid];
        sval[tid] = g_val[m * KN + tid];
    }
    if (tid >= 32 && tid < 35) {
        sctr[tid - 32] = pos[3 * idx[m] + (tid - 32)];
    }
    __syncthreads();

    // ---- gather features transposed into A: rows 0..63 = x[nbr], 64..66 = rel
    {
        const int e = tid >> 2, q = tid & 3;
        const int n = snbr[e];
        const float4* xr = (const float4*)(x + n * DIN);
        #pragma unroll
        for (int j = 0; j < 4; j++) {
            float4 v = __ldg(xr + q * 4 + j);
            int i0 = q * 16 + j * 4;
            A[(i0 + 0) * APAD + e] = v.x;
            A[(i0 + 1) * APAD + e] = v.y;
            A[(i0 + 2) * APAD + e] = v.z;
            A[(i0 + 3) * APAD + e] = v.w;
        }
        if (q == 3) {
            A[64 * APAD + e] = pos[3 * n]     - sctr[0];
            A[65 * APAD + e] = pos[3 * n + 1] - sctr[1];
            A[66 * APAD + e] = pos[3 * n + 2] - sctr[2];
        }
    }
    __syncthreads();

    layer_fc<67, 128>(A, W1, b1, Bsh, c0, r0);
    __syncthreads();
    layer_fc<128, 128>(Bsh, W2, b2, A, c0, r0);
    __syncthreads();

    #pragma unroll
    for (int half = 0; half < 2; half++) {
        layer_fc_max<128, 256>(A, W3, b3, sval, part, c0 + half * 128, r0, rg, g);
        __syncthreads();
        {
            float mm = part[tid];
            mm = fmaxf(mm, part[128 + tid]);
            mm = fmaxf(mm, part[256 + tid]);
            mm = fmaxf(mm, part[384 + tid]);
            out[(size_t)m * 256 + half * 128 + tid] = mm;
        }
        __syncthreads();
    }

    // tail outputs: pos[idx] then batch[idx] (as float)
    if (tid < 3)  out[(size_t)MC * 256 + (size_t)m * 3 + tid] = sctr[tid];
    if (tid == 3) out[(size_t)MC * 259 + m] = (float)batch[idx[m]];
}

// ============================================================================
extern "C" void kernel_launch(void* const* d_in, const int* in_sizes, int n_in,
                              void* d_out, int out_size)
{
    const float* x     = (const float*)d_in[0];
    const float* pos   = (const float*)d_in[1];
    const int*   batch = (const int*)  d_in[2];
    const int*   idx   = (const int*)  d_in[3];
    const float* W1    = (const float*)d_in[4];
    const float* b1    = (const float*)d_in[5];
    const float* W2    = (const float*)d_in[6];
    const float* b2    = (const float*)d_in[7];
    const float* W3    = (const float*)d_in[8];
    const float* b3    = (const float*)d_in[9];
    float* out = (float*)d_out;

    knn_kernel<<<MC, 256>>>(pos, batch, idx);
    mlp_kernel<<<MC, 128>>>(x, pos, batch, idx, W1, b1, W2, b2, W3, b3, out);
}

// round 5
// speedup vs baseline: 1.2856x; 1.2856x over previous
#include <cuda_runtime.h>
#include <math.h>

// Problem constants (fixed by the dataset)
#define NTOT 32768
#define NB   8
#define DIN  64
#define MC   8192
#define KN   32
#define PPC  4096           // points per cloud = NTOT/NB
#define R2   0.04f          // radius^2

// ---------------- scratch (static device arrays; no allocation) -------------
__device__ int g_nbr[MC * KN];
__device__ int g_val[MC * KN];

// ---------------- packed fp32x2 FMA (sm_100+ PTX) ---------------------------
__device__ __forceinline__ float2 ffma2(float2 a, float2 b, float2 c) {
    float2 d;
    asm("fma.rn.f32x2 %0, %1, %2, %3;"
        : "=l"(reinterpret_cast<unsigned long long&>(d))
        : "l"(reinterpret_cast<unsigned long long&>(a)),
          "l"(reinterpret_cast<unsigned long long&>(b)),
          "l"(reinterpret_cast<unsigned long long&>(c)));
    return d;
}

// monotonic fp32 -> uint32 (handles negative-epsilon d2 from rounding)
__device__ __forceinline__ unsigned int fkey(float f) {
    unsigned int b = __float_as_uint(f);
    return b ^ ((b & 0x80000000u) ? 0xFFFFFFFFu : 0x80000000u);
}

// ============================================================================
// Kernel 1 (v2): ball-filtered exact KNN.
// Only neighbors with d2 <= R^2 can contribute to the masked max, and every
// in-ball point sorts before every out-of-ball point, so:
//   contributing set == min(C,32) smallest (d2, idx) among in-ball candidates.
// One block per center, 256 threads:
//   phase 1: each thread computes d2 for 16 candidates (registers).
//   phase 2: ballot-compact in-ball candidates into shared as 64-bit keys
//            ((monotonic d2 bits) << 12 | j)  -> exact top_k tie-break order.
//   phase 3: warp 0 runs min(C,32) argmin rounds over the tiny C-list (~137).
// ============================================================================
__global__ __launch_bounds__(256) void knn_kernel(
    const float* __restrict__ pos,
    const int*   __restrict__ batch,
    const int*   __restrict__ idx)
{
    __shared__ unsigned long long cand[PPC];
    __shared__ int  woff[9];
    __shared__ float sc[4];
    __shared__ int   sbase;

    const int m    = blockIdx.x;
    const int tid  = threadIdx.x;
    const int lane = tid & 31, w = tid >> 5;

    if (tid == 0) {
        int ci = idx[m];
        float cx = pos[3 * ci], cy = pos[3 * ci + 1], cz = pos[3 * ci + 2];
        sc[0] = cx; sc[1] = cy; sc[2] = cz;
        sc[3] = cx * cx + cy * cy + cz * cz;
        sbase = batch[ci] * PPC;
    }
    __syncthreads();

    const float cx = sc[0], cy = sc[1], cz = sc[2], cc = sc[3];
    const int base = sbase;

    // ---- phase 1: distances (identical expression to the reference form)
    float d2r[PPC / 256];
    int   cnt = 0;
    #pragma unroll
    for (int r = 0; r < PPC / 256; r++) {
        int j = tid + r * 256;
        const float* p = pos + 3 * (base + j);
        float px = p[0], py = p[1], pz = p[2];
        float pp  = px * px + py * py + pz * pz;
        float dot = cx * px + cy * py + cz * pz;
        float d2  = (cc + pp) - 2.0f * dot;
        d2r[r] = d2;
        cnt += (d2 <= R2) ? 1 : 0;
    }
    // warp total
    #pragma unroll
    for (int off = 16; off; off >>= 1) cnt += __shfl_down_sync(0xffffffffu, cnt, off);
    if (lane == 0) woff[w] = cnt;
    __syncthreads();
    if (tid == 0) {
        int acc = 0;
        #pragma unroll
        for (int t = 0; t < 8; t++) { int c = woff[t]; woff[t] = acc; acc += c; }
        woff[8] = acc;   // C
    }
    __syncthreads();

    // ---- phase 2: ballot compaction (no atomics)
    {
        int off = woff[w];
        #pragma unroll
        for (int r = 0; r < PPC / 256; r++) {
            int j = tid + r * 256;
            bool pred = (d2r[r] <= R2);
            unsigned int mask = __ballot_sync(0xffffffffu, pred);
            if (pred) {
                int p = off + __popc(mask & ((1u << lane) - 1u));
                cand[p] = ((unsigned long long)fkey(d2r[r]) << 12) | (unsigned)j;
            }
            off += __popc(mask);
        }
    }
    __syncthreads();

    // ---- phase 3: warp 0 selects min(C,32) smallest keys
    if (w == 0) {
        const int C = woff[8];
        const unsigned long long SENT = 0xFFFFFFFFFFFFFFFFull;
        for (int k = 0; k < KN; k++) {
            unsigned long long best = SENT;
            int bslot = -1;
            for (int s = lane; s < C; s += 32) {
                unsigned long long v = cand[s];
                if (v < best) { best = v; bslot = s; }
            }
            #pragma unroll
            for (int off = 16; off; off >>= 1) {
                unsigned long long ov = __shfl_down_sync(0xffffffffu, best, off);
                int os = __shfl_down_sync(0xffffffffu, bslot, off);
                if (ov < best) { best = ov; bslot = os; }
            }
            // lane 0 owns the result
            if (lane == 0) {
                if (best != SENT) {
                    g_nbr[m * KN + k] = base + (int)(best & 0xFFFu);
                    g_val[m * KN + k] = 1;
                    cand[bslot] = SENT;            // remove winner
                } else {
                    g_nbr[m * KN + k] = base;      // arbitrary, masked out
                    g_val[m * KN + k] = 0;
                }
            }
            __syncwarp();
        }
    }
}

// ============================================================================
// Kernel 2: edge MLP + masked max aggregation (unchanged from R1).
// ============================================================================
#define APAD 34

template <int DINL, int COLS>
__device__ __forceinline__ void layer_fc(
    const float* __restrict__ Ash, const float* __restrict__ W,
    const float* __restrict__ bias, float* __restrict__ Bout,
    int c0, int r0)
{
    float2 acc[4][4];
    #pragma unroll
    for (int ccx = 0; ccx < 4; ccx++) {
        float b = __ldg(bias + c0 + ccx);
        #pragma unroll
        for (int q = 0; q < 4; q++) acc[q][ccx] = make_float2(b, b);
    }
    #pragma unroll 4
    for (int i = 0; i < DINL; i++) {
        float4 wv = __ldg((const float4*)(W + i * COLS + c0));
        float2 wp[4] = { make_float2(wv.x, wv.x), make_float2(wv.y, wv.y),
                         make_float2(wv.z, wv.z), make_float2(wv.w, wv.w) };
        const float2* arow = (const float2*)(Ash + i * APAD + r0);
        float2 a0 = arow[0], a1 = arow[1], a2 = arow[2], a3 = arow[3];
        #pragma unroll
        for (int ccx = 0; ccx < 4; ccx++) {
            acc[0][ccx] = ffma2(a0, wp[ccx], acc[0][ccx]);
            acc[1][ccx] = ffma2(a1, wp[ccx], acc[1][ccx]);
            acc[2][ccx] = ffma2(a2, wp[ccx], acc[2][ccx]);
            acc[3][ccx] = ffma2(a3, wp[ccx], acc[3][ccx]);
        }
    }
    #pragma unroll
    for (int ccx = 0; ccx < 4; ccx++)
        #pragma unroll
        for (int q = 0; q < 4; q++) {
            float2 v = acc[q][ccx];
            v.x = fmaxf(v.x, 0.0f);
            v.y = fmaxf(v.y, 0.0f);
            *(float2*)(Bout + (c0 + ccx) * APAD + r0 + 2 * q) = v;
        }
}

template <int DINL, int COLS>
__device__ __forceinline__ void layer_fc_max(
    const float* __restrict__ Ash, const float* __restrict__ W,
    const float* __restrict__ bias, const int* __restrict__ sval,
    float* __restrict__ part, int c0, int r0, int rg, int g)
{
    float2 acc[4][4];
    #pragma unroll
    for (int ccx = 0; ccx < 4; ccx++) {
        float b = __ldg(bias + c0 + ccx);
        #pragma unroll
        for (int q = 0; q < 4; q++) acc[q][ccx] = make_float2(b, b);
    }
    #pragma unroll 4
    for (int i = 0; i < DINL; i++) {
        float4 wv = __ldg((const float4*)(W + i * COLS + c0));
        float2 wp[4] = { make_float2(wv.x, wv.x), make_float2(wv.y, wv.y),
                         make_float2(wv.z, wv.z), make_float2(wv.w, wv.w) };
        const float2* arow = (const float2*)(Ash + i * APAD + r0);
        float2 a0 = arow[0], a1 = arow[1], a2 = arow[2], a3 = arow[3];
        #pragma unroll
        for (int ccx = 0; ccx < 4; ccx++) {
            acc[0][ccx] = ffma2(a0, wp[ccx], acc[0][ccx]);
            acc[1][ccx] = ffma2(a1, wp[ccx], acc[1][ccx]);
            acc[2][ccx] = ffma2(a2, wp[ccx], acc[2][ccx]);
            acc[3][ccx] = ffma2(a3, wp[ccx], acc[3][ccx]);
        }
    }
    const float NEGINF = __int_as_float(0xff800000);
    #pragma unroll
    for (int ccx = 0; ccx < 4; ccx++) {
        float mm = NEGINF;
        #pragma unroll
        for (int q = 0; q < 4; q++) {
            float2 v = acc[q][ccx];
            float hx = fmaxf(v.x, 0.0f);
            float hy = fmaxf(v.y, 0.0f);
            if (sval[r0 + 2 * q])     mm = fmaxf(mm, hx);
            if (sval[r0 + 2 * q + 1]) mm = fmaxf(mm, hy);
        }
        part[rg * 128 + g * 4 + ccx] = mm;
    }
}

__global__ __launch_bounds__(128) void mlp_kernel(
    const float* __restrict__ x,   const float* __restrict__ pos,
    const int*   __restrict__ batch, const int* __restrict__ idx,
    const float* __restrict__ W1, const float* __restrict__ b1,
    const float* __restrict__ W2, const float* __restrict__ b2,
    const float* __restrict__ W3, const float* __restrict__ b3,
    float* __restrict__ out)
{
    __shared__ __align__(16) float A[128 * APAD];
    __shared__ __align__(16) float Bsh[128 * APAD];
    __shared__ float part[512];
    __shared__ int   snbr[KN];
    __shared__ int   sval[KN];
    __shared__ float sctr[3];

    const int m   = blockIdx.x;
    const int tid = threadIdx.x;
    const int g   = tid & 31;        // column group
    const int rg  = tid >> 5;        // row group
    const int c0  = g * 4;
    const int r0  = rg * 8;

    if (tid < KN) {
        snbr[tid] = g_nbr[m * KN + tid];
        sval[tid] = g_val[m * KN + tid];
    }
    if (tid >= 32 && tid < 35) {
        sctr[tid - 32] = pos[3 * idx[m] + (tid - 32)];
    }
    __syncthreads();

    // ---- gather features transposed into A: rows 0..63 = x[nbr], 64..66 = rel
    {
        const int e = tid >> 2, q = tid & 3;
        const int n = snbr[e];
        const float4* xr = (const float4*)(x + n * DIN);
        #pragma unroll
        for (int j = 0; j < 4; j++) {
            float4 v = __ldg(xr + q * 4 + j);
            int i0 = q * 16 + j * 4;
            A[(i0 + 0) * APAD + e] = v.x;
            A[(i0 + 1) * APAD + e] = v.y;
            A[(i0 + 2) * APAD + e] = v.z;
            A[(i0 + 3) * APAD + e] = v.w;
        }
        if (q == 3) {
            A[64 * APAD + e] = pos[3 * n]     - sctr[0];
            A[65 * APAD + e] = pos[3 * n + 1] - sctr[1];
            A[66 * APAD + e] = pos[3 * n + 2] - sctr[2];
        }
    }
    __syncthreads();

    layer_fc<67, 128>(A, W1, b1, Bsh, c0, r0);
    __syncthreads();
    layer_fc<128, 128>(Bsh, W2, b2, A, c0, r0);
    __syncthreads();

    #pragma unroll
    for (int half = 0; half < 2; half++) {
        layer_fc_max<128, 256>(A, W3, b3, sval, part, c0 + half * 128, r0, rg, g);
        __syncthreads();
        {
            float mm = part[tid];
            mm = fmaxf(mm, part[128 + tid]);
            mm = fmaxf(mm, part[256 + tid]);
            mm = fmaxf(mm, part[384 + tid]);
            out[(size_t)m * 256 + half * 128 + tid] = mm;
        }
        __syncthreads();
    }

    // tail outputs: pos[idx] then batch[idx] (as float)
    if (tid < 3)  out[(size_t)MC * 256 + (size_t)m * 3 + tid] = sctr[tid];
    if (tid == 3) out[(size_t)MC * 259 + m] = (float)batch[idx[m]];
}

// ============================================================================
extern "C" void kernel_launch(void* const* d_in, const int* in_sizes, int n_in,
                              void* d_out, int out_size)
{
    const float* x     = (const float*)d_in[0];
    const float* pos   = (const float*)d_in[1];
    const int*   batch = (const int*)  d_in[2];
    const int*   idx   = (const int*)  d_in[3];
    const float* W1    = (const float*)d_in[4];
    const float* b1    = (const float*)d_in[5];
    const float* W2    = (const float*)d_in[6];
    const float* b2    = (const float*)d_in[7];
    const float* W3    = (const float*)d_in[8];
    const float* b3    = (const float*)d_in[9];
    float* out = (float*)d_out;

    knn_kernel<<<MC, 256>>>(pos, batch, idx);
    mlp_kernel<<<MC, 128>>>(x, pos, batch, idx, W1, b1, W2, b2, W3, b3, out);
}

// round 10
// speedup vs baseline: 2.9708x; 2.3109x over previous
#include <cuda_runtime.h>
#include <cuda_bf16.h>
#include <math.h>
#include <stdint.h>

// ---------------- problem constants ----------------
#define NTOT 32768
#define NB   8
#define DIN  64
#define MC   8192
#define KN   32
#define PPC  4096
#define R2   0.04f

// ---------------- fragment-image geometry ----------------
// B images are stored fragment-linear: tile (kt,nt) -> 32 lanes x uint2 {b0,b1}
// b0 = {B[tig*2][grp], B[tig*2+1][grp]}, b1 = rows +8  (PTX m16n8k16 layout)
#define L1_KT 5          // K=80 (67 padded)
#define L2_KT 8          // K=128
#define L3_KT 8          // K=128
#define OFF_L1H 0
#define OFF_L1L (OFF_L1H + L1_KT * 16 * 32)
#define OFF_L2H (OFF_L1L + L1_KT * 16 * 32)
#define OFF_L2L (OFF_L2H + L2_KT * 16 * 32)
#define OFF_L3H (OFF_L2L + L2_KT * 16 * 32)
#define OFF_L3L (OFF_L3H + L3_KT * 32 * 32)
#define B_TOTAL (OFF_L3L + L3_KT * 32 * 32)   // uint2 units

// ---------------- scratch ----------------
__device__ int   g_nbr[MC * KN];
__device__ int   g_val[MC * KN];
__device__ uint2 g_B[B_TOTAL];

// A image: per warp [32 rows][256 bf16 cols] = 16KB, swizzled:
//   addr(row, chunk) = warpbase + row*512 + ((chunk ^ (row&7)) * 16)
// hi activation at cols 0..127 (chunks 0..15), lo at cols 128..255 (chunks 16..31).
#define WARP_A_BYTES 16384
#define SMEM_BYTES   (4 * WARP_A_BYTES + 512 * 4)

// ========================= helpers =========================
__device__ __forceinline__ uint32_t smem_u32(const void* p) {
    uint32_t a;
    asm("{ .reg .u64 t; cvta.to.shared.u64 t, %1; cvt.u32.u64 %0, t; }" : "=r"(a) : "l"(p));
    return a;
}
__device__ __forceinline__ void sts32(uint32_t a, uint32_t v) {
    asm volatile("st.shared.b32 [%0], %1;" :: "r"(a), "r"(v));
}
__device__ __forceinline__ void sts128(uint32_t a, uint32_t v0, uint32_t v1, uint32_t v2, uint32_t v3) {
    asm volatile("st.shared.v4.b32 [%0], {%1,%2,%3,%4};" :: "r"(a), "r"(v0), "r"(v1), "r"(v2), "r"(v3));
}
__device__ __forceinline__ void ldsm4(uint32_t* r, uint32_t addr) {
    asm volatile("ldmatrix.sync.aligned.m8n8.x4.shared.b16 {%0,%1,%2,%3}, [%4];"
                 : "=r"(r[0]), "=r"(r[1]), "=r"(r[2]), "=r"(r[3]) : "r"(addr));
}
__device__ __forceinline__ void mma_bf16(float* c, const uint32_t* a, uint2 b) {
    asm volatile("mma.sync.aligned.m16n8k16.row.col.f32.bf16.bf16.f32 "
                 "{%0,%1,%2,%3}, {%4,%5,%6,%7}, {%8,%9}, {%0,%1,%2,%3};"
                 : "+f"(c[0]), "+f"(c[1]), "+f"(c[2]), "+f"(c[3])
                 : "r"(a[0]), "r"(a[1]), "r"(a[2]), "r"(a[3]), "r"(b.x), "r"(b.y));
}
// pack (a,b) -> bf16x2 hi (a in low half) and residual lo pair
__device__ __forceinline__ void split2(float a, float b, uint32_t& hi, uint32_t& lo) {
    asm("cvt.rn.satfinite.bf16x2.f32 %0, %1, %2;" : "=r"(hi) : "f"(b), "f"(a));
    float ha = __uint_as_float(hi << 16);
    float hb = __uint_as_float(hi & 0xFFFF0000u);
    float ra = a - ha, rb = b - hb;
    asm("cvt.rn.satfinite.bf16x2.f32 %0, %1, %2;" : "=r"(lo) : "f"(rb), "f"(ra));
}
__device__ __forceinline__ unsigned int fkey(float f) {
    unsigned int b = __float_as_uint(f);
    return b ^ ((b & 0x80000000u) ? 0xFFFFFFFFu : 0x80000000u);
}

// ============================================================================
// Kernel 0a: zero the fragment images (covers K-padding rows of layer 1)
// ============================================================================
__global__ void zero_w_kernel() {
    uint32_t* p = (uint32_t*)g_B;
    int n = B_TOTAL * 2;
    for (int i = blockIdx.x * blockDim.x + threadIdx.x; i < n; i += gridDim.x * blockDim.x)
        p[i] = 0;
}

// ============================================================================
// Kernel 0b: fp32 weights -> bf16 hi/lo fragment-linear images
// ============================================================================
__global__ void conv_w_kernel(const float* __restrict__ W1,
                              const float* __restrict__ W2,
                              const float* __restrict__ W3) {
    int e = blockIdx.x * blockDim.x + threadIdx.x;
    int k, n, NTS; float v; unsigned baseH, baseL;
    if (e < 67 * 128) {
        k = e / 128; n = e % 128; v = W1[e]; NTS = 16;
        baseH = OFF_L1H * 4u; baseL = OFF_L1L * 4u;
    } else if (e < 67 * 128 + 128 * 128) {
        int i = e - 67 * 128; k = i / 128; n = i % 128; v = W2[i]; NTS = 16;
        baseH = OFF_L2H * 4u; baseL = OFF_L2L * 4u;
    } else if (e < 67 * 128 + 128 * 128 + 128 * 256) {
        int i = e - 67 * 128 - 128 * 128; k = i / 256; n = i % 256; v = W3[i]; NTS = 32;
        baseH = OFF_L3H * 4u; baseL = OFF_L3L * 4u;
    } else return;

    __nv_bfloat16 hb = __float2bfloat16_rn(v);
    float hf = __bfloat162float(hb);
    __nv_bfloat16 lb = __float2bfloat16_rn(v - hf);

    int kt = k >> 4, kin = k & 15, nt = n >> 3, nin = n & 7;
    int lane = nin * 4 + ((kin & 7) >> 1);
    int reg  = kin >> 3;
    int half = kin & 1;
    unsigned idx = ((unsigned)(kt * NTS + nt) * 32 + lane) * 4 + reg * 2 + half;
    unsigned short* B = (unsigned short*)g_B;
    B[baseH + idx] = __bfloat16_as_ushort(hb);
    B[baseL + idx] = __bfloat16_as_ushort(lb);
}

// ============================================================================
// Kernel 1: ball-filtered exact KNN with parallel rank selection.
// ============================================================================
#define CANDCAP 2048
__global__ __launch_bounds__(256) void knn_kernel(
    const float* __restrict__ pos,
    const int*   __restrict__ batch,
    const int*   __restrict__ idx)
{
    __shared__ unsigned long long cand[CANDCAP];
    __shared__ int  woff[9];
    __shared__ float sc[4];
    __shared__ int   sbase;

    const int m    = blockIdx.x;
    const int tid  = threadIdx.x;
    const int lane = tid & 31, w = tid >> 5;

    if (tid == 0) {
        int ci = idx[m];
        float cx = pos[3 * ci], cy = pos[3 * ci + 1], cz = pos[3 * ci + 2];
        sc[0] = cx; sc[1] = cy; sc[2] = cz;
        sc[3] = cx * cx + cy * cy + cz * cz;
        sbase = batch[ci] * PPC;
    }
    __syncthreads();

    const float cx = sc[0], cy = sc[1], cz = sc[2], cc = sc[3];
    const int base = sbase;

    float d2r[PPC / 256];
    int cnt = 0;
    #pragma unroll
    for (int r = 0; r < PPC / 256; r++) {
        int j = tid + r * 256;
        const float* p = pos + 3 * (base + j);
        float px = p[0], py = p[1], pz = p[2];
        float pp  = px * px + py * py + pz * pz;
        float dot = cx * px + cy * py + cz * pz;
        float d2  = (cc + pp) - 2.0f * dot;
        d2r[r] = d2;
        cnt += (d2 <= R2) ? 1 : 0;
    }
    #pragma unroll
    for (int off = 16; off; off >>= 1) cnt += __shfl_down_sync(0xffffffffu, cnt, off);
    if (lane == 0) woff[w] = cnt;
    __syncthreads();
    if (tid == 0) {
        int acc = 0;
        #pragma unroll
        for (int t = 0; t < 8; t++) { int c = woff[t]; woff[t] = acc; acc += c; }
        woff[8] = acc;
    }
    __syncthreads();

    {
        int off = woff[w];
        #pragma unroll
        for (int r = 0; r < PPC / 256; r++) {
            int j = tid + r * 256;
            bool pred = (d2r[r] <= R2);
            unsigned int mask = __ballot_sync(0xffffffffu, pred);
            if (pred) {
                int p = off + __popc(mask & ((1u << lane) - 1u));
                if (p < CANDCAP)
                    cand[p] = ((unsigned long long)fkey(d2r[r]) << 12) | (unsigned)j;
            }
            off += __popc(mask);
        }
    }
    __syncthreads();

    const int C = min(woff[8], CANDCAP);
    for (int s = tid; s < C; s += 256) {
        unsigned long long key = cand[s];
        int rank = 0;
        for (int t = 0; t < C; t++) rank += (cand[t] < key) ? 1 : 0;
        if (rank < KN) {
            g_nbr[m * KN + rank] = base + (int)(key & 0xFFFu);
            g_val[m * KN + rank] = 1;
        }
    }
    if (tid >= C && tid < KN) {
        g_nbr[m * KN + tid] = base;
        g_val[m * KN + tid] = 0;
    }
}

// ============================================================================
// Warp-level GEMM over the warp's 32-row A image.
//   acc[m][nt][4] += Ah*Bh + Al*Bh + Ah*Bl   (bf16x3 -> ~fp32 precision)
// ============================================================================
template <int KT, int NT, int NTS>
__device__ __forceinline__ void gemm_acc(uint32_t abase,
                                         const uint2* __restrict__ Bh,
                                         const uint2* __restrict__ Bl,
                                         int ntoff, int lane,
                                         float (&acc)[2][16][4])
{
    #pragma unroll
    for (int m = 0; m < 2; m++)
        #pragma unroll
        for (int nt = 0; nt < NT; nt++)
            #pragma unroll
            for (int q = 0; q < 4; q++) acc[m][nt][q] = 0.0f;

    const int i = lane >> 3, jj = lane & 7;
    const int cpart = i >> 1;
    const uint32_t rb0 = abase + (uint32_t)(jj + (i & 1) * 8) * 512;
    const uint32_t rb1 = rb0 + 16 * 512;

    for (int kt = 0; kt < KT; kt++) {
        uint32_t ch = (uint32_t)((kt * 2 + cpart) ^ jj) << 4;
        uint32_t ah0[4], ah1[4], al0[4], al1[4];
        ldsm4(ah0, rb0 + ch);
        ldsm4(ah1, rb1 + ch);
        ldsm4(al0, rb0 + ch + 256);
        ldsm4(al1, rb1 + ch + 256);
        const uint2* bph = Bh + (size_t)(kt * NTS + ntoff) * 32 + lane;
        const uint2* bpl = Bl + (size_t)(kt * NTS + ntoff) * 32 + lane;
        #pragma unroll
        for (int nt = 0; nt < NT; nt++) {
            uint2 bh = __ldg(bph + nt * 32);
            mma_bf16(acc[0][nt], ah0, bh);
            mma_bf16(acc[1][nt], ah1, bh);
            mma_bf16(acc[0][nt], al0, bh);
            mma_bf16(acc[1][nt], al1, bh);
            uint2 bl = __ldg(bpl + nt * 32);
            mma_bf16(acc[0][nt], ah0, bl);
            mma_bf16(acc[1][nt], ah1, bl);
        }
    }
}

// mid-layer epilogue: bias + relu + bf16 hi/lo split -> back into A image
__device__ __forceinline__ void epi_mid(float (&acc)[2][16][4],
                                        const float* __restrict__ bias,
                                        uint32_t abase, int lane)
{
    const int grp = lane >> 2, tig = lane & 3;
    #pragma unroll
    for (int nt = 0; nt < 16; nt++) {
        float b0 = bias[nt * 8 + tig * 2];
        float b1 = bias[nt * 8 + tig * 2 + 1];
        #pragma unroll
        for (int m = 0; m < 2; m++) {
            int row0 = m * 16 + grp, row1 = row0 + 8;
            float v0 = fmaxf(acc[m][nt][0] + b0, 0.0f);
            float v1 = fmaxf(acc[m][nt][1] + b1, 0.0f);
            float v2 = fmaxf(acc[m][nt][2] + b0, 0.0f);
            float v3 = fmaxf(acc[m][nt][3] + b1, 0.0f);
            uint32_t h0, l0, h1, l1;
            split2(v0, v1, h0, l0);
            split2(v2, v3, h1, l1);
            uint32_t r0b = abase + row0 * 512, r1b = abase + row1 * 512;
            sts32(r0b + ((uint32_t)(nt ^ (row0 & 7)) << 4) + tig * 4, h0);
            sts32(r0b + ((uint32_t)((16 + nt) ^ (row0 & 7)) << 4) + tig * 4, l0);
            sts32(r1b + ((uint32_t)(nt ^ (row1 & 7)) << 4) + tig * 4, h1);
            sts32(r1b + ((uint32_t)((16 + nt) ^ (row1 & 7)) << 4) + tig * 4, l1);
        }
    }
}

// final epilogue: bias + relu + masked max over 32 edges, write 128 cols
__device__ __forceinline__ void epi_out(float (&acc)[2][16][4],
                                        const float* __restrict__ bias,
                                        unsigned vmask, float* __restrict__ outp,
                                        int lane)
{
    const int grp = lane >> 2, tig = lane & 3;
    #pragma unroll
    for (int nt = 0; nt < 16; nt++) {
        float b0 = bias[nt * 8 + tig * 2];
        float b1 = bias[nt * 8 + tig * 2 + 1];
        float p0 = 0.0f, p1 = 0.0f;
        #pragma unroll
        for (int m = 0; m < 2; m++) {
            int r0 = m * 16 + grp, r1 = r0 + 8;
            bool k0 = (vmask >> r0) & 1, k1 = (vmask >> r1) & 1;
            float v0 = k0 ? fmaxf(acc[m][nt][0] + b0, 0.0f) : 0.0f;
            float v1 = k0 ? fmaxf(acc[m][nt][1] + b1, 0.0f) : 0.0f;
            float v2 = k1 ? fmaxf(acc[m][nt][2] + b0, 0.0f) : 0.0f;
            float v3 = k1 ? fmaxf(acc[m][nt][3] + b1, 0.0f) : 0.0f;
            p0 = fmaxf(p0, fmaxf(v0, v2));
            p1 = fmaxf(p1, fmaxf(v1, v3));
        }
        #pragma unroll
        for (int off = 4; off <= 16; off <<= 1) {
            p0 = fmaxf(p0, __shfl_xor_sync(0xffffffffu, p0, off));
            p1 = fmaxf(p1, __shfl_xor_sync(0xffffffffu, p1, off));
        }
        if (grp == 0)
            *(float2*)(outp + nt * 8 + tig * 2) = make_float2(p0, p1);
    }
}

// ============================================================================
// Kernel 2: warp-per-center fused MLP on mma.sync tensor cores.
// ============================================================================
__global__ __launch_bounds__(128) void mlp_kernel(
    const float* __restrict__ x,   const float* __restrict__ pos,
    const int*   __restrict__ batch, const int* __restrict__ idx,
    const float* __restrict__ b1, const float* __restrict__ b2,
    const float* __restrict__ b3, float* __restrict__ out)
{
    extern __shared__ __align__(16) unsigned char smem[];
    float* biasSh = (float*)(smem + 4 * WARP_A_BYTES);

    const int tid = threadIdx.x;
    const int lane = tid & 31, w = tid >> 5;
    const int c = blockIdx.x * 4 + w;

    for (int i = tid; i < 512; i += 128) {
        float bv = (i < 128) ? __ldg(b1 + i) : (i < 256) ? __ldg(b2 + i - 128) : __ldg(b3 + i - 256);
        biasSh[i] = bv;
    }
    __syncthreads();

    const uint32_t abase = smem_u32(smem) + (uint32_t)w * WARP_A_BYTES;

    // ---- per-lane edge
    const int nb  = __ldg((const int*)g_nbr + c * KN + lane);
    const int vld = __ldg((const int*)g_val + c * KN + lane);
    const int ci  = __ldg(idx + c);
    const float cpx = __ldg(pos + 3 * ci), cpy = __ldg(pos + 3 * ci + 1), cpz = __ldg(pos + 3 * ci + 2);
    const unsigned vmask = __ballot_sync(0xffffffffu, vld);

    // ---- gather row = lane into A image (hi cols 0..79, lo cols 128..207)
    {
        const uint32_t rowbase = abase + (uint32_t)lane * 512;
        const int r7 = lane & 7;
        const float4* xr = (const float4*)(x + (size_t)nb * DIN);
        #pragma unroll
        for (int q = 0; q < 16; q++) {
            float4 v = __ldg(xr + q);
            uint32_t h0, l0, h1, l1;
            split2(v.x, v.y, h0, l0);
            split2(v.z, v.w, h1, l1);
            uint32_t bo = ((uint32_t)(q & 1)) << 3;
            uint32_t chH = ((uint32_t)((q >> 1) ^ r7)) << 4;
            uint32_t chL = ((uint32_t)((16 + (q >> 1)) ^ r7)) << 4;
            sts32(rowbase + chH + bo, h0);
            sts32(rowbase + chH + bo + 4, h1);
            sts32(rowbase + chL + bo, l0);
            sts32(rowbase + chL + bo + 4, l1);
        }
        float rx = __ldg(pos + 3 * nb)     - cpx;
        float ry = __ldg(pos + 3 * nb + 1) - cpy;
        float rz = __ldg(pos + 3 * nb + 2) - cpz;
        uint32_t hA, lA, hB, lB;
        split2(rx, ry, hA, lA);
        split2(rz, 0.0f, hB, lB);
        sts128(rowbase + ((uint32_t)(8 ^ r7) << 4), hA, hB, 0u, 0u);       // cols 64..71 hi
        sts128(rowbase + ((uint32_t)(9 ^ r7) << 4), 0u, 0u, 0u, 0u);       // cols 72..79 hi
        sts128(rowbase + ((uint32_t)(24 ^ r7) << 4), lA, lB, 0u, 0u);      // cols 64..71 lo
        sts128(rowbase + ((uint32_t)(25 ^ r7) << 4), 0u, 0u, 0u, 0u);      // cols 72..79 lo
    }
    __syncwarp();

    float acc[2][16][4];

    // layer 1: K=80 -> 128
    gemm_acc<L1_KT, 16, 16>(abase, g_B + OFF_L1H, g_B + OFF_L1L, 0, lane, acc);
    __syncwarp();
    epi_mid(acc, biasSh, abase, lane);
    __syncwarp();

    // layer 2: 128 -> 128
    gemm_acc<L2_KT, 16, 16>(abase, g_B + OFF_L2H, g_B + OFF_L2L, 0, lane, acc);
    __syncwarp();
    epi_mid(acc, biasSh + 128, abase, lane);
    __syncwarp();

    // layer 3: 128 -> 256 in two 128-col chunks, fused masked max
    gemm_acc<L3_KT, 16, 32>(abase, g_B + OFF_L3H, g_B + OFF_L3L, 0, lane, acc);
    epi_out(acc, biasSh + 256, vmask, out + (size_t)c * 256, lane);
    gemm_acc<L3_KT, 16, 32>(abase, g_B + OFF_L3H, g_B + OFF_L3L, 16, lane, acc);
    epi_out(acc, biasSh + 384, vmask, out + (size_t)c * 256 + 128, lane);

    // tails: pos[idx] then batch[idx]
    if (lane == 0) out[(size_t)MC * 256 + (size_t)c * 3 + 0] = cpx;
    if (lane == 1) out[(size_t)MC * 256 + (size_t)c * 3 + 1] = cpy;
    if (lane == 2) out[(size_t)MC * 256 + (size_t)c * 3 + 2] = cpz;
    if (lane == 3) out[(size_t)MC * 259 + c] = (float)__ldg(batch + ci);
}

// ============================================================================
extern "C" void kernel_launch(void* const* d_in, const int* in_sizes, int n_in,
                              void* d_out, int out_size)
{
    const float* x     = (const float*)d_in[0];
    const float* pos   = (const float*)d_in[1];
    const int*   batch = (const int*)  d_in[2];
    const int*   idx   = (const int*)  d_in[3];
    const float* W1    = (const float*)d_in[4];
    const float* b1    = (const float*)d_in[5];
    const float* W2    = (const float*)d_in[6];
    const float* b2    = (const float*)d_in[7];
    const float* W3    = (const float*)d_in[8];
    const float* b3    = (const float*)d_in[9];
    float* out = (float*)d_out;

    cudaFuncSetAttribute(mlp_kernel, cudaFuncAttributeMaxDynamicSharedMemorySize, SMEM_BYTES);

    zero_w_kernel<<<64, 256>>>();
    conv_w_kernel<<<(67 * 128 + 128 * 128 + 128 * 256 + 255) / 256, 256>>>(W1, W2, W3);
    knn_kernel<<<MC, 256>>>(pos, batch, idx);
    mlp_kernel<<<MC / 4, 128, SMEM_BYTES>>>(x, pos, batch, idx, b1, b2, b3, out);
}